// round 2
// baseline (speedup 1.0000x reference)
#include <cuda_runtime.h>
#include <cstdint>
#include <cstddef>

#define TT 1024
#define BB 64
#define DD 512
#define HH 512

// Recurrence partition: NI batch-groups x NJ hidden-slices
#define NI 8
#define NJ 16
#define BSL (BB / NI)   // 8 batch rows per group
#define HSL (HH / NJ)   // 32 hidden units per slice

// Device scratch (no cudaMalloc allowed)
__device__ float g_Z [(size_t)TT * BB * HH];   // pre-activation buffer (reused per layer)
__device__ float g_Y0[(size_t)TT * BB * HH];   // layer-0 output sequence
__device__ int   g_prog[NI][NJ];               // per-CTA progress counters

__global__ void reset_flags_kernel() {
    int t = threadIdx.x;
    if (t < NI * NJ) ((int*)g_prog)[t] = 0;
}

__device__ __forceinline__ int ld_acquire_gpu(const int* p) {
    int v;
    asm volatile("ld.acquire.gpu.global.b32 %0, [%1];" : "=r"(v) : "l"(p) : "memory");
    return v;
}
__device__ __forceinline__ void st_release_gpu(int* p, int v) {
    asm volatile("st.release.gpu.global.b32 [%0], %1;" :: "l"(p), "r"(v) : "memory");
}

// ---------------------------------------------------------------------------
// Input GEMM: C[M,HH] = A[M,K] @ W[HH,K]^T + b1[n] + b2[n]
// Tiles: BM=128, BN=64, BK=16; 256 threads; 8x4 register micro-tile.
// ---------------------------------------------------------------------------
__global__ __launch_bounds__(256) void gemm_bias_kernel(
    const float* __restrict__ A, const float* __restrict__ W,
    const float* __restrict__ b1, const float* __restrict__ b2,
    float* __restrict__ C, int M, int K)
{
    __shared__ float As[16][132];  // [k][m], padded
    __shared__ float Ws[16][68];   // [k][n], padded

    const int m0  = blockIdx.x * 128;
    const int n0  = blockIdx.y * 64;
    const int tid = threadIdx.x;
    const int tm  = (tid & 15) * 8;
    const int tn  = (tid >> 4) * 4;

    float acc[8][4];
#pragma unroll
    for (int i = 0; i < 8; i++)
#pragma unroll
        for (int j = 0; j < 4; j++) acc[i][j] = 0.0f;

    for (int k0 = 0; k0 < K; k0 += 16) {
        // Load A tile (128x16) transposed into As
#pragma unroll
        for (int r = 0; r < 2; r++) {
            int idx = tid * 2 + r;                 // 0..511
            int row = idx >> 2;                    // 0..127
            int c4  = (idx & 3) * 4;               // 0,4,8,12
            float4 v = *(const float4*)&A[(size_t)(m0 + row) * K + k0 + c4];
            As[c4 + 0][row] = v.x; As[c4 + 1][row] = v.y;
            As[c4 + 2][row] = v.z; As[c4 + 3][row] = v.w;
        }
        // Load W tile (64x16) transposed into Ws
        {
            int row = tid >> 2;                    // 0..63
            int c4  = (tid & 3) * 4;
            float4 v = *(const float4*)&W[(size_t)(n0 + row) * K + k0 + c4];
            Ws[c4 + 0][row] = v.x; Ws[c4 + 1][row] = v.y;
            Ws[c4 + 2][row] = v.z; Ws[c4 + 3][row] = v.w;
        }
        __syncthreads();

#pragma unroll
        for (int k = 0; k < 16; k++) {
            float a[8], b[4];
#pragma unroll
            for (int i = 0; i < 8; i++) a[i] = As[k][tm + i];
#pragma unroll
            for (int j = 0; j < 4; j++) b[j] = Ws[k][tn + j];
#pragma unroll
            for (int i = 0; i < 8; i++)
#pragma unroll
                for (int j = 0; j < 4; j++)
                    acc[i][j] = fmaf(a[i], b[j], acc[i][j]);
        }
        __syncthreads();
    }

#pragma unroll
    for (int j = 0; j < 4; j++) {
        int n = n0 + tn + j;
        float bias = b1[n] + b2[n];
#pragma unroll
        for (int i = 0; i < 8; i++)
            C[(size_t)(m0 + tm + i) * HH + n] = acc[i][j] + bias;
    }
}

// ---------------------------------------------------------------------------
// Persistent recurrence kernel.
// Grid (NJ, NI) = 128 CTAs, 256 threads. CTA (j, i) computes hidden slice
// [j*32, j*32+32) for batch rows [i*8, i*8+8) across all T steps.
// Whh slice held in registers: warp kc (0..7) lane l owns
// Whh[j*32 + l][kc*64 .. kc*64+63].  h broadcast from SMEM.
// Cross-CTA (same batch group) exchange via per-CTA progress counters:
// reader waits on ALL NJ producers' counters (min-progress, skew <= 1).
// ---------------------------------------------------------------------------
__global__ __launch_bounds__(256, 1) void recur_kernel(
    const float* __restrict__ Z, const float* __restrict__ Whh,
    float* __restrict__ Y)
{
    __shared__ float hs[BSL][HH];          // 16 KB: full h for this batch group
    __shared__ float red[BSL][8][32];      // 8 KB: partial sums [b][kc][j]

    const int j    = blockIdx.x;           // hidden slice
    const int i    = blockIdx.y;           // batch group
    const int tid  = threadIdx.x;
    const int kc   = tid >> 5;             // warp id = k-chunk 0..7
    const int lane = tid & 31;             // local hidden index 0..31
    const int b0   = i * BSL;

    // Load my W chunk into registers (one-time)
    float w[64];
    {
        const float* wrow = Whh + (size_t)(j * HSL + lane) * HH + kc * 64;
#pragma unroll
        for (int q = 0; q < 16; q++) {
            float4 v = *(const float4*)(wrow + q * 4);
            w[q * 4 + 0] = v.x; w[q * 4 + 1] = v.y;
            w[q * 4 + 2] = v.z; w[q * 4 + 3] = v.w;
        }
    }

    const int rb = tid >> 5;               // reduce phase: batch row 0..7
    const int rj = tid & 31;               // reduce phase: hidden idx 0..31
    const int brow = b0 + rb;
    const int jg   = j * HSL + rj;

    for (int t = 0; t < TT; t++) {
        float part[BSL];
#pragma unroll
        for (int b = 0; b < BSL; b++) part[b] = 0.0f;

        if (t > 0) {
            // Wait until EVERY producer CTA of this batch group finished t-1.
            if (tid < NJ) {
                while (ld_acquire_gpu(&g_prog[i][tid]) < t) { }
            }
            __syncthreads();

            // Load h = Y[t-1][b0..b0+7][:] into SMEM (L2 path, bypass L1)
            const float4* hp = (const float4*)(Y + ((size_t)(t - 1) * BB + b0) * HH);
            float4* hsf = (float4*)&hs[0][0];
#pragma unroll
            for (int r = 0; r < (BSL * HH / 4) / 256; r++) {
                int v = tid + r * 256;
                hsf[v] = __ldcg(hp + v);
            }
            __syncthreads();

            // part[b] = sum_k hs[b][kc*64+k] * w[k]
#pragma unroll
            for (int b = 0; b < BSL; b++) {
                const float4* hrow = (const float4*)&hs[b][kc * 64];
#pragma unroll
                for (int q = 0; q < 16; q++) {
                    float4 h4 = hrow[q];
                    part[b] = fmaf(h4.x, w[q * 4 + 0], part[b]);
                    part[b] = fmaf(h4.y, w[q * 4 + 1], part[b]);
                    part[b] = fmaf(h4.z, w[q * 4 + 2], part[b]);
                    part[b] = fmaf(h4.w, w[q * 4 + 3], part[b]);
                }
            }
#pragma unroll
            for (int b = 0; b < BSL; b++) red[b][kc][lane] = part[b];
            __syncthreads();
        }

        // Reduce over the 8 k-chunks, add pre-activation, tanh, write h
        float acc = 0.0f;
        if (t > 0) {
#pragma unroll
            for (int c = 0; c < 8; c++) acc += red[rb][c][rj];
        }
        float val = tanhf(acc + Z[((size_t)t * BB + brow) * HH + jg]);
        Y[((size_t)t * BB + brow) * HH + jg] = val;

        // Publish: all writes of step t visible before counter = t+1.
        __threadfence();
        __syncthreads();
        if (tid == 0) st_release_gpu(&g_prog[i][j], t + 1);
    }
}

// ---------------------------------------------------------------------------
extern "C" void kernel_launch(void* const* d_in, const int* in_sizes, int n_in,
                              void* d_out, int out_size)
{
    const float* Xt   = (const float*)d_in[0];
    const float* ihW0 = (const float*)d_in[1];
    const float* ihB0 = (const float*)d_in[2];
    const float* hhW0 = (const float*)d_in[3];
    const float* hhB0 = (const float*)d_in[4];
    const float* ihW1 = (const float*)d_in[5];
    const float* ihB1 = (const float*)d_in[6];
    const float* hhW1 = (const float*)d_in[7];
    const float* hhB1 = (const float*)d_in[8];
    float* out = (float*)d_out;

    float *zp = nullptr, *y0p = nullptr;
    cudaGetSymbolAddress((void**)&zp,  g_Z);
    cudaGetSymbolAddress((void**)&y0p, g_Y0);

    dim3 ggrid(TT * BB / 128, HH / 64);
    dim3 rgrid(NJ, NI);

    // Layer 0: Z = Xt @ ihW0^T + ihB0 + hhB0; then recurrence -> g_Y0
    gemm_bias_kernel<<<ggrid, 256>>>(Xt, ihW0, ihB0, hhB0, zp, TT * BB, DD);
    reset_flags_kernel<<<1, 128>>>();
    recur_kernel<<<rgrid, 256>>>(zp, hhW0, y0p);

    // Layer 1: Z = y0 @ ihW1^T + ihB1 + hhB1; then recurrence -> out
    gemm_bias_kernel<<<ggrid, 256>>>(y0p, ihW1, ihB1, hhB1, zp, TT * BB, HH);
    reset_flags_kernel<<<1, 128>>>();
    recur_kernel<<<rgrid, 256>>>(zp, hhW1, out);
}

// round 3
// speedup vs baseline: 1.7868x; 1.7868x over previous
#include <cuda_runtime.h>
#include <cstdint>
#include <cstddef>

#define TT 1024
#define BB 64
#define DD 512
#define HH 512

// Recurrence partition: NI batch-groups x NJ hidden-slices (NI*NJ = 128 CTAs)
#define NI 16
#define NJ 8
#define BSL (BB / NI)   // 4 batch rows per group
#define HSL (HH / NJ)   // 64 hidden units per slice
#define KC  4           // k-chunks (128 k each)

// Device scratch (no cudaMalloc allowed)
__device__ float g_Z [(size_t)TT * BB * HH];   // pre-activation buffer (reused per layer)
__device__ float g_Y0[(size_t)TT * BB * HH];   // layer-0 output sequence
__device__ int   g_prog[NI][NJ];               // per-CTA progress counters

__global__ void reset_flags_kernel() {
    int t = threadIdx.x;
    if (t < NI * NJ) ((int*)g_prog)[t] = 0;
}

__device__ __forceinline__ int ld_acquire_gpu(const int* p) {
    int v;
    asm volatile("ld.acquire.gpu.global.b32 %0, [%1];" : "=r"(v) : "l"(p) : "memory");
    return v;
}
__device__ __forceinline__ void st_release_gpu(int* p, int v) {
    asm volatile("st.release.gpu.global.b32 [%0], %1;" :: "l"(p), "r"(v) : "memory");
}

// ---------------------------------------------------------------------------
// Input GEMM: C[M,HH] = A[M,K] @ W[HH,K]^T + b1[n] + b2[n]
// BM=128, BN=128, BK=16; 256 threads; 8x8 micro-tile; double-buffered SMEM,
// one __syncthreads per k-tile.
// ---------------------------------------------------------------------------
__global__ __launch_bounds__(256) void gemm_bias_kernel(
    const float* __restrict__ A, const float* __restrict__ W,
    const float* __restrict__ b1, const float* __restrict__ b2,
    float* __restrict__ C, int M, int K)
{
    __shared__ float As[2][16][132];  // [buf][k][m]
    __shared__ float Ws[2][16][132];  // [buf][k][n]

    const int m0  = blockIdx.x * 128;
    const int n0  = blockIdx.y * 128;
    const int tid = threadIdx.x;
    const int tx  = tid & 15;          // n-dir
    const int ty  = tid >> 4;          // m-dir

    // Each thread loads 2 float4 of A and 2 float4 of W per tile.
    // float4 id v in [0,512): row = v>>2 (0..127), c4 = (v&3)*4
    const int v0 = tid, v1 = tid + 256;
    const int r0 = v0 >> 2, c0 = (v0 & 3) * 4;
    const int r1 = v1 >> 2, c1 = (v1 & 3) * 4;

    const float* A0 = A + (size_t)(m0 + r0) * K + c0;
    const float* A1 = A + (size_t)(m0 + r1) * K + c1;
    const float* W0 = W + (size_t)(n0 + r0) * K + c0;
    const float* W1 = W + (size_t)(n0 + r1) * K + c1;

    float4 ra0, ra1, rw0, rw1;

    // Prologue: load tile 0
    ra0 = *(const float4*)A0;  ra1 = *(const float4*)A1;
    rw0 = *(const float4*)W0;  rw1 = *(const float4*)W1;
    As[0][c0 + 0][r0] = ra0.x; As[0][c0 + 1][r0] = ra0.y;
    As[0][c0 + 2][r0] = ra0.z; As[0][c0 + 3][r0] = ra0.w;
    As[0][c1 + 0][r1] = ra1.x; As[0][c1 + 1][r1] = ra1.y;
    As[0][c1 + 2][r1] = ra1.z; As[0][c1 + 3][r1] = ra1.w;
    Ws[0][c0 + 0][r0] = rw0.x; Ws[0][c0 + 1][r0] = rw0.y;
    Ws[0][c0 + 2][r0] = rw0.z; Ws[0][c0 + 3][r0] = rw0.w;
    Ws[0][c1 + 0][r1] = rw1.x; Ws[0][c1 + 1][r1] = rw1.y;
    Ws[0][c1 + 2][r1] = rw1.z; Ws[0][c1 + 3][r1] = rw1.w;
    __syncthreads();

    float acc[8][8];
#pragma unroll
    for (int i = 0; i < 8; i++)
#pragma unroll
        for (int j = 0; j < 8; j++) acc[i][j] = 0.0f;

    const int NT = K / 16;
    for (int kt = 0; kt < NT; kt++) {
        const int p = kt & 1;
        if (kt + 1 < NT) {
            const int koff = (kt + 1) * 16;
            ra0 = *(const float4*)(A0 + koff);
            ra1 = *(const float4*)(A1 + koff);
            rw0 = *(const float4*)(W0 + koff);
            rw1 = *(const float4*)(W1 + koff);
        }

#pragma unroll
        for (int k = 0; k < 16; k++) {
            float4 a0 = *(const float4*)&As[p][k][ty * 8];
            float4 a1 = *(const float4*)&As[p][k][ty * 8 + 4];
            float4 bq0 = *(const float4*)&Ws[p][k][tx * 8];
            float4 bq1 = *(const float4*)&Ws[p][k][tx * 8 + 4];
            float a[8] = {a0.x, a0.y, a0.z, a0.w, a1.x, a1.y, a1.z, a1.w};
            float b[8] = {bq0.x, bq0.y, bq0.z, bq0.w, bq1.x, bq1.y, bq1.z, bq1.w};
#pragma unroll
            for (int i = 0; i < 8; i++)
#pragma unroll
                for (int j = 0; j < 8; j++)
                    acc[i][j] = fmaf(a[i], b[j], acc[i][j]);
        }

        if (kt + 1 < NT) {
            const int q = p ^ 1;
            As[q][c0 + 0][r0] = ra0.x; As[q][c0 + 1][r0] = ra0.y;
            As[q][c0 + 2][r0] = ra0.z; As[q][c0 + 3][r0] = ra0.w;
            As[q][c1 + 0][r1] = ra1.x; As[q][c1 + 1][r1] = ra1.y;
            As[q][c1 + 2][r1] = ra1.z; As[q][c1 + 3][r1] = ra1.w;
            Ws[q][c0 + 0][r0] = rw0.x; Ws[q][c0 + 1][r0] = rw0.y;
            Ws[q][c0 + 2][r0] = rw0.z; Ws[q][c0 + 3][r0] = rw0.w;
            Ws[q][c1 + 0][r1] = rw1.x; Ws[q][c1 + 1][r1] = rw1.y;
            Ws[q][c1 + 2][r1] = rw1.z; Ws[q][c1 + 3][r1] = rw1.w;
            __syncthreads();
        }
    }

    // Epilogue: add bias, write 8x8
    float bias[8];
#pragma unroll
    for (int j = 0; j < 8; j++) {
        int n = n0 + tx * 8 + j;
        bias[j] = b1[n] + b2[n];
    }
#pragma unroll
    for (int i = 0; i < 8; i++) {
        float* crow = C + (size_t)(m0 + ty * 8 + i) * HH + n0 + tx * 8;
        float4 o0 = make_float4(acc[i][0] + bias[0], acc[i][1] + bias[1],
                                acc[i][2] + bias[2], acc[i][3] + bias[3]);
        float4 o1 = make_float4(acc[i][4] + bias[4], acc[i][5] + bias[5],
                                acc[i][6] + bias[6], acc[i][7] + bias[7]);
        *(float4*)(crow)     = o0;
        *(float4*)(crow + 4) = o1;
    }
}

// ---------------------------------------------------------------------------
// Persistent recurrence kernel.
// Grid (NJ, NI) = 128 CTAs, 256 threads. CTA (j, i) computes hidden slice
// [j*64, j*64+64) for batch rows [i*4, i*4+4) across all T steps.
// Thread layout (compute): kc = tid>>6 (k-chunk of 128), jloc = tid&63.
// Whh held in registers: w[128] = Whh[j*64+jloc][kc*128 .. +127].
// Cross-CTA exchange via per-producer progress counters (skew <= 1).
// Z[t] prefetched with __ldcs before the spin so DRAM latency is hidden.
// ---------------------------------------------------------------------------
__global__ __launch_bounds__(256, 1) void recur_kernel(
    const float* __restrict__ Z, const float* __restrict__ Whh,
    float* __restrict__ Y)
{
    __shared__ float hs[BSL][HH];            // 8 KB: full h for this batch group
    __shared__ float red[BSL][KC][HSL];      // 4 KB: partial sums

    const int j    = blockIdx.x;             // hidden slice
    const int i    = blockIdx.y;             // batch group
    const int tid  = threadIdx.x;
    const int kc   = tid >> 6;               // 0..3
    const int jloc = tid & 63;               // 0..63
    const int b0   = i * BSL;

    // Load my W chunk into registers (one-time): 128 floats
    float w[128];
    {
        const float* wrow = Whh + (size_t)(j * HSL + jloc) * HH + kc * 128;
#pragma unroll
        for (int q = 0; q < 32; q++) {
            float4 v = *(const float4*)(wrow + q * 4);
            w[q * 4 + 0] = v.x; w[q * 4 + 1] = v.y;
            w[q * 4 + 2] = v.z; w[q * 4 + 3] = v.w;
        }
    }

    // Reduce-phase layout: rb = batch row (0..3), rjj = hidden idx (0..63)
    const int rb  = tid >> 6;
    const int rjj = tid & 63;
    const int brow = b0 + rb;
    const int jg   = j * HSL + rjj;
    const size_t zy_off = (size_t)brow * HH + jg;

    for (int t = 0; t < TT; t++) {
        // Prefetch this step's pre-activation BEFORE waiting (DRAM latency
        // overlaps spin + h-load + compute).
        float zv = __ldcs(Z + (size_t)t * BB * HH + zy_off);

        float acc = 0.0f;
        if (t > 0) {
            // Wait until EVERY producer CTA of this batch group finished t-1.
            if (tid < NJ) {
                while (ld_acquire_gpu(&g_prog[i][tid]) < t) { }
            }
            __syncthreads();

            // Load h = Y[t-1][b0..b0+3][:] into SMEM (L2 path)
            const float4* hp = (const float4*)(Y + ((size_t)(t - 1) * BB + b0) * HH);
            float4* hsf = (float4*)&hs[0][0];
#pragma unroll
            for (int r = 0; r < (BSL * HH / 4) / 256; r++) {
                int v = tid + r * 256;
                hsf[v] = __ldcg(hp + v);
            }
            __syncthreads();

            // part[b] = sum over this thread's 128-k chunk of hs[b][*] * w[*]
            float part[BSL];
#pragma unroll
            for (int b = 0; b < BSL; b++) part[b] = 0.0f;
#pragma unroll
            for (int b = 0; b < BSL; b++) {
                const float4* hrow = (const float4*)&hs[b][kc * 128];
#pragma unroll
                for (int q = 0; q < 32; q++) {
                    float4 h4 = hrow[q];
                    part[b] = fmaf(h4.x, w[q * 4 + 0], part[b]);
                    part[b] = fmaf(h4.y, w[q * 4 + 1], part[b]);
                    part[b] = fmaf(h4.z, w[q * 4 + 2], part[b]);
                    part[b] = fmaf(h4.w, w[q * 4 + 3], part[b]);
                }
            }
#pragma unroll
            for (int b = 0; b < BSL; b++) red[b][kc][jloc] = part[b];
            __syncthreads();

#pragma unroll
            for (int c = 0; c < KC; c++) acc += red[rb][c][rjj];
        }

        // h_new = tanh(acc + z); publish
        float val = tanhf(acc + zv);
        Y[(size_t)t * BB * HH + zy_off] = val;

        __syncthreads();   // all STG issued before the release store below
        if (tid == 0) st_release_gpu(&g_prog[i][j], t + 1);
    }
}

// ---------------------------------------------------------------------------
extern "C" void kernel_launch(void* const* d_in, const int* in_sizes, int n_in,
                              void* d_out, int out_size)
{
    const float* Xt   = (const float*)d_in[0];
    const float* ihW0 = (const float*)d_in[1];
    const float* ihB0 = (const float*)d_in[2];
    const float* hhW0 = (const float*)d_in[3];
    const float* hhB0 = (const float*)d_in[4];
    const float* ihW1 = (const float*)d_in[5];
    const float* ihB1 = (const float*)d_in[6];
    const float* hhW1 = (const float*)d_in[7];
    const float* hhB1 = (const float*)d_in[8];
    float* out = (float*)d_out;

    float *zp = nullptr, *y0p = nullptr;
    cudaGetSymbolAddress((void**)&zp,  g_Z);
    cudaGetSymbolAddress((void**)&y0p, g_Y0);

    dim3 ggrid(TT * BB / 128, HH / 128);
    dim3 rgrid(NJ, NI);

    // Layer 0: Z = Xt @ ihW0^T + ihB0 + hhB0; then recurrence -> g_Y0
    gemm_bias_kernel<<<ggrid, 256>>>(Xt, ihW0, ihB0, hhB0, zp, TT * BB, DD);
    reset_flags_kernel<<<1, 128>>>();
    recur_kernel<<<rgrid, 256>>>(zp, hhW0, y0p);

    // Layer 1: Z = y0 @ ihW1^T + ihB1 + hhB1; then recurrence -> out
    gemm_bias_kernel<<<ggrid, 256>>>(y0p, ihW1, ihB1, hhB1, zp, TT * BB, HH);
    reset_flags_kernel<<<1, 128>>>();
    recur_kernel<<<rgrid, 256>>>(zp, hhW1, out);
}

// round 4
// speedup vs baseline: 1.7870x; 1.0001x over previous
#include <cuda_runtime.h>
#include <cstdint>
#include <cstddef>

#define TT 1024
#define BB 64
#define DD 512
#define HH 512

// Recurrence partition: NI batch-groups (clusters) x NJ hidden-slices (CTAs/cluster)
#define NI 16
#define NJ 8
#define BSL (BB / NI)        // 4 batch rows per group
#define HSL (HH / NJ)        // 64 hidden units per slice
#define KC  4                // k-chunks of 128
#define HS_BYTES (BSL * HH * 4)   // 8192 bytes per h buffer

// Device scratch (no cudaMalloc allowed)
__device__ float g_Z [(size_t)TT * BB * HH];   // pre-activation buffer (reused per layer)
__device__ float g_Y0[(size_t)TT * BB * HH];   // layer-0 output sequence

// ---------------------------------------------------------------------------
// PTX helpers
// ---------------------------------------------------------------------------
__device__ __forceinline__ uint32_t smem_u32(const void* p) {
    uint32_t a;
    asm("{ .reg .u64 t; cvta.to.shared.u64 t, %1; cvt.u32.u64 %0, t; }"
        : "=r"(a) : "l"(p));
    return a;
}
__device__ __forceinline__ uint32_t mapa_u32(uint32_t addr, uint32_t rank) {
    uint32_t r;
    asm("mapa.shared::cluster.u32 %0, %1, %2;" : "=r"(r) : "r"(addr), "r"(rank));
    return r;
}
__device__ __forceinline__ void mbar_init(uint32_t mbar, uint32_t cnt) {
    asm volatile("mbarrier.init.shared.b64 [%0], %1;" :: "r"(mbar), "r"(cnt) : "memory");
}
__device__ __forceinline__ void mbar_arrive_expect_tx(uint32_t mbar, uint32_t tx) {
    asm volatile("mbarrier.arrive.expect_tx.shared.b64 _, [%0], %1;"
                 :: "r"(mbar), "r"(tx) : "memory");
}
__device__ __forceinline__ void mbar_wait_parity(uint32_t mbar, uint32_t parity) {
    asm volatile(
        "{\n\t"
        ".reg .pred P;\n\t"
        "WAIT_%=:\n\t"
        "mbarrier.try_wait.parity.acquire.cta.shared::cta.b64 P, [%0], %1, 0x989680;\n\t"
        "@P bra.uni DONE_%=;\n\t"
        "bra.uni WAIT_%=;\n\t"
        "DONE_%=:\n\t"
        "}"
        :: "r"(mbar), "r"(parity) : "memory");
}
__device__ __forceinline__ void st_async_f32(uint32_t raddr, float v, uint32_t rmbar) {
    asm volatile(
        "st.async.shared::cluster.mbarrier::complete_tx::bytes.b32 [%0], %1, [%2];"
        :: "r"(raddr), "r"(__float_as_uint(v)), "r"(rmbar) : "memory");
}

// ---------------------------------------------------------------------------
// Input GEMM: C[M,HH] = A[M,K] @ W[HH,K]^T + b1[n] + b2[n]
// BM=128, BN=128, BK=16; 256 threads; 8x8 micro-tile; double-buffered SMEM.
// ---------------------------------------------------------------------------
__global__ __launch_bounds__(256) void gemm_bias_kernel(
    const float* __restrict__ A, const float* __restrict__ W,
    const float* __restrict__ b1, const float* __restrict__ b2,
    float* __restrict__ C, int M, int K)
{
    __shared__ float As[2][16][132];
    __shared__ float Ws[2][16][132];

    const int m0  = blockIdx.x * 128;
    const int n0  = blockIdx.y * 128;
    const int tid = threadIdx.x;
    const int tx  = tid & 15;
    const int ty  = tid >> 4;

    const int v0 = tid, v1 = tid + 256;
    const int r0 = v0 >> 2, c0 = (v0 & 3) * 4;
    const int r1 = v1 >> 2, c1 = (v1 & 3) * 4;

    const float* A0 = A + (size_t)(m0 + r0) * K + c0;
    const float* A1 = A + (size_t)(m0 + r1) * K + c1;
    const float* W0 = W + (size_t)(n0 + r0) * K + c0;
    const float* W1 = W + (size_t)(n0 + r1) * K + c1;

    float4 ra0, ra1, rw0, rw1;

    ra0 = *(const float4*)A0;  ra1 = *(const float4*)A1;
    rw0 = *(const float4*)W0;  rw1 = *(const float4*)W1;
    As[0][c0 + 0][r0] = ra0.x; As[0][c0 + 1][r0] = ra0.y;
    As[0][c0 + 2][r0] = ra0.z; As[0][c0 + 3][r0] = ra0.w;
    As[0][c1 + 0][r1] = ra1.x; As[0][c1 + 1][r1] = ra1.y;
    As[0][c1 + 2][r1] = ra1.z; As[0][c1 + 3][r1] = ra1.w;
    Ws[0][c0 + 0][r0] = rw0.x; Ws[0][c0 + 1][r0] = rw0.y;
    Ws[0][c0 + 2][r0] = rw0.z; Ws[0][c0 + 3][r0] = rw0.w;
    Ws[0][c1 + 0][r1] = rw1.x; Ws[0][c1 + 1][r1] = rw1.y;
    Ws[0][c1 + 2][r1] = rw1.z; Ws[0][c1 + 3][r1] = rw1.w;
    __syncthreads();

    float acc[8][8];
#pragma unroll
    for (int i = 0; i < 8; i++)
#pragma unroll
        for (int j = 0; j < 8; j++) acc[i][j] = 0.0f;

    const int NT = K / 16;
    for (int kt = 0; kt < NT; kt++) {
        const int p = kt & 1;
        if (kt + 1 < NT) {
            const int koff = (kt + 1) * 16;
            ra0 = *(const float4*)(A0 + koff);
            ra1 = *(const float4*)(A1 + koff);
            rw0 = *(const float4*)(W0 + koff);
            rw1 = *(const float4*)(W1 + koff);
        }

#pragma unroll
        for (int k = 0; k < 16; k++) {
            float4 a0 = *(const float4*)&As[p][k][ty * 8];
            float4 a1 = *(const float4*)&As[p][k][ty * 8 + 4];
            float4 bq0 = *(const float4*)&Ws[p][k][tx * 8];
            float4 bq1 = *(const float4*)&Ws[p][k][tx * 8 + 4];
            float a[8] = {a0.x, a0.y, a0.z, a0.w, a1.x, a1.y, a1.z, a1.w};
            float b[8] = {bq0.x, bq0.y, bq0.z, bq0.w, bq1.x, bq1.y, bq1.z, bq1.w};
#pragma unroll
            for (int i = 0; i < 8; i++)
#pragma unroll
                for (int j = 0; j < 8; j++)
                    acc[i][j] = fmaf(a[i], b[j], acc[i][j]);
        }

        if (kt + 1 < NT) {
            const int q = p ^ 1;
            As[q][c0 + 0][r0] = ra0.x; As[q][c0 + 1][r0] = ra0.y;
            As[q][c0 + 2][r0] = ra0.z; As[q][c0 + 3][r0] = ra0.w;
            As[q][c1 + 0][r1] = ra1.x; As[q][c1 + 1][r1] = ra1.y;
            As[q][c1 + 2][r1] = ra1.z; As[q][c1 + 3][r1] = ra1.w;
            Ws[q][c0 + 0][r0] = rw0.x; Ws[q][c0 + 1][r0] = rw0.y;
            Ws[q][c0 + 2][r0] = rw0.z; Ws[q][c0 + 3][r0] = rw0.w;
            Ws[q][c1 + 0][r1] = rw1.x; Ws[q][c1 + 1][r1] = rw1.y;
            Ws[q][c1 + 2][r1] = rw1.z; Ws[q][c1 + 3][r1] = rw1.w;
            __syncthreads();
        }
    }

    float bias[8];
#pragma unroll
    for (int j = 0; j < 8; j++) {
        int n = n0 + tx * 8 + j;
        bias[j] = b1[n] + b2[n];
    }
#pragma unroll
    for (int i = 0; i < 8; i++) {
        float* crow = C + (size_t)(m0 + ty * 8 + i) * HH + n0 + tx * 8;
        float4 o0 = make_float4(acc[i][0] + bias[0], acc[i][1] + bias[1],
                                acc[i][2] + bias[2], acc[i][3] + bias[3]);
        float4 o1 = make_float4(acc[i][4] + bias[4], acc[i][5] + bias[5],
                                acc[i][6] + bias[6], acc[i][7] + bias[7]);
        *(float4*)(crow)     = o0;
        *(float4*)(crow + 4) = o1;
    }
}

// ---------------------------------------------------------------------------
// Persistent recurrence kernel with cluster DSMEM all-gather.
// Grid (NJ, NI), cluster (NJ,1,1): cluster = one batch group (rows i*4..i*4+3),
// CTA rank j in cluster owns hidden slice [j*64, j*64+64).
// Each step: wait local mbarrier (expect_tx = full 8KB h for this group),
// compute from local hs buffer, then st.async each new h value into all 8
// cluster CTAs' hs buffers (auto tx-signal on their mbarrier). Double-buffered.
// ---------------------------------------------------------------------------
__global__ __launch_bounds__(256, 1) __cluster_dims__(NJ, 1, 1)
void recur_kernel(
    const float* __restrict__ Z, const float* __restrict__ Whh,
    float* __restrict__ Y)
{
    __shared__ float hs[2][BSL][HH];              // 16 KB double-buffered h
    __shared__ float red[BSL][KC][HSL];           // 4 KB partial sums
    __shared__ alignas(8) unsigned long long mbar[2];

    const int j    = blockIdx.x;                  // hidden slice = cluster rank
    const int i    = blockIdx.y;                  // batch group
    const int tid  = threadIdx.x;
    const int kc   = tid >> 6;                    // 0..3
    const int jloc = tid & 63;                    // 0..63
    const int b0   = i * BSL;

    const uint32_t hs_base   = smem_u32(&hs[0][0][0]);
    const uint32_t mbar_base = smem_u32(&mbar[0]);

    // Init mbarriers + arm phase 0 of both (arrive count = 1, tx = 8 KB)
    if (tid == 0) {
        mbar_init(mbar_base + 0, 1);
        mbar_init(mbar_base + 8, 1);
        mbar_arrive_expect_tx(mbar_base + 0, HS_BYTES);
        mbar_arrive_expect_tx(mbar_base + 8, HS_BYTES);
    }
    // Make mbarrier init visible cluster-wide before any peer st.async
    asm volatile("barrier.cluster.arrive.aligned;" ::: "memory");
    asm volatile("barrier.cluster.wait.aligned;"  ::: "memory");

    // Precompute peer SMEM addresses (hs base + mbar base per rank)
    uint32_t peer_hs[NJ], peer_mb[NJ];
#pragma unroll
    for (int p = 0; p < NJ; p++) {
        peer_hs[p] = mapa_u32(hs_base,   (uint32_t)p);
        peer_mb[p] = mapa_u32(mbar_base, (uint32_t)p);
    }

    // Load my Whh chunk into registers (128 floats)
    float w[128];
    {
        const float* wrow = Whh + (size_t)(j * HSL + jloc) * HH + kc * 128;
#pragma unroll
        for (int q = 0; q < 32; q++) {
            float4 v = *(const float4*)(wrow + q * 4);
            w[q * 4 + 0] = v.x; w[q * 4 + 1] = v.y;
            w[q * 4 + 2] = v.z; w[q * 4 + 3] = v.w;
        }
    }

    // Output mapping: rb = batch row 0..3, rjj = hidden idx within slice
    const int rb  = tid >> 6;
    const int rjj = tid & 63;
    const int brow = b0 + rb;
    const int jg   = j * HSL + rjj;                       // global hidden idx
    const size_t   zy_off  = (size_t)brow * HH + jg;
    const uint32_t out_off = (uint32_t)(rb * HH + jg) * 4; // byte off in hs buf

    int par0 = 0, par1 = 0;

    for (int t = 0; t < TT; t++) {
        const int ph = t & 1;

        // Prefetch this step's pre-activation (DRAM latency overlaps wait)
        float zv = __ldcs(Z + (size_t)t * BB * HH + zy_off);

        float acc = 0.0f;
        if (t > 0) {
            // Wait for full h(t-1) (8 KB of st.async deliveries)
            if (ph == 0) { mbar_wait_parity(mbar_base + 0, par0); par0 ^= 1; }
            else         { mbar_wait_parity(mbar_base + 8, par1); par1 ^= 1; }
            // Re-arm this barrier for its next use (step t+2). tid0 re-arms
            // BEFORE its own broadcast below, and no peer can target this
            // phase until it has received tid0's broadcast -> safe order.
            if (tid == 0)
                mbar_arrive_expect_tx(mbar_base + (ph ? 8 : 0), HS_BYTES);

            // part[b] = dot over this thread's 128-wide k chunk
            float part[BSL];
#pragma unroll
            for (int b = 0; b < BSL; b++) part[b] = 0.0f;
#pragma unroll
            for (int b = 0; b < BSL; b++) {
                const float4* hrow = (const float4*)&hs[ph][b][kc * 128];
#pragma unroll
                for (int q = 0; q < 32; q++) {
                    float4 h4 = hrow[q];
                    part[b] = fmaf(h4.x, w[q * 4 + 0], part[b]);
                    part[b] = fmaf(h4.y, w[q * 4 + 1], part[b]);
                    part[b] = fmaf(h4.z, w[q * 4 + 2], part[b]);
                    part[b] = fmaf(h4.w, w[q * 4 + 3], part[b]);
                }
            }
#pragma unroll
            for (int b = 0; b < BSL; b++) red[b][kc][jloc] = part[b];
            __syncthreads();

#pragma unroll
            for (int c = 0; c < KC; c++) acc += red[rb][c][rjj];
        }

        // h_new = tanh(acc + z)
        float val = tanhf(acc + zv);
        Y[(size_t)t * BB * HH + zy_off] = val;

        // Broadcast h value into every cluster CTA's hs[ph^1] buffer,
        // signaling their mbarrier's tx count.
        if (t + 1 < TT) {
            const uint32_t off  = (uint32_t)(ph ^ 1) * HS_BYTES + out_off;
            const uint32_t moff = (uint32_t)(ph ^ 1) * 8;
#pragma unroll
            for (int p = 0; p < NJ; p++)
                st_async_f32(peer_hs[p] + off, val, peer_mb[p] + moff);
        }

        __syncthreads();   // protect red[] reuse next iteration
    }
}

// ---------------------------------------------------------------------------
extern "C" void kernel_launch(void* const* d_in, const int* in_sizes, int n_in,
                              void* d_out, int out_size)
{
    const float* Xt   = (const float*)d_in[0];
    const float* ihW0 = (const float*)d_in[1];
    const float* ihB0 = (const float*)d_in[2];
    const float* hhW0 = (const float*)d_in[3];
    const float* hhB0 = (const float*)d_in[4];
    const float* ihW1 = (const float*)d_in[5];
    const float* ihB1 = (const float*)d_in[6];
    const float* hhW1 = (const float*)d_in[7];
    const float* hhB1 = (const float*)d_in[8];
    float* out = (float*)d_out;

    float *zp = nullptr, *y0p = nullptr;
    cudaGetSymbolAddress((void**)&zp,  g_Z);
    cudaGetSymbolAddress((void**)&y0p, g_Y0);

    dim3 ggrid(TT * BB / 128, HH / 128);
    dim3 rgrid(NJ, NI);

    // Layer 0
    gemm_bias_kernel<<<ggrid, 256>>>(Xt, ihW0, ihB0, hhB0, zp, TT * BB, DD);
    recur_kernel<<<rgrid, 256>>>(zp, hhW0, y0p);

    // Layer 1
    gemm_bias_kernel<<<ggrid, 256>>>(y0p, ihW1, ihB1, hhB1, zp, TT * BB, HH);
    recur_kernel<<<rgrid, 256>>>(zp, hhW1, out);
}

// round 5
// speedup vs baseline: 1.8098x; 1.0128x over previous
#include <cuda_runtime.h>
#include <cstdint>
#include <cstddef>

#define TT 1024
#define BB 64
#define DD 512
#define HH 512

// Recurrence partition: NI batch-groups (clusters) x NJ hidden-slices (CTAs/cluster)
#define NI 16
#define NJ 8
#define BSL (BB / NI)        // 4 batch rows per group
#define HSL (HH / NJ)        // 64 hidden units per slice
#define KC  4                // k-chunks of 128 per CTA (one per warp-pair)
#define SLICE_BYTES (BSL * HSL * 4)      // 1024 bytes per CTA contribution
#define HS_BYTES (NJ * SLICE_BYTES)      // 8192 bytes per h buffer

// Device scratch (no cudaMalloc allowed)
__device__ float g_Z [(size_t)TT * BB * HH];
__device__ float g_Y0[(size_t)TT * BB * HH];

// ---------------------------------------------------------------------------
// PTX helpers
// ---------------------------------------------------------------------------
__device__ __forceinline__ uint32_t smem_u32(const void* p) {
    uint32_t a;
    asm("{ .reg .u64 t; cvta.to.shared.u64 t, %1; cvt.u32.u64 %0, t; }"
        : "=r"(a) : "l"(p));
    return a;
}
__device__ __forceinline__ uint32_t mapa_u32(uint32_t addr, uint32_t rank) {
    uint32_t r;
    asm("mapa.shared::cluster.u32 %0, %1, %2;" : "=r"(r) : "r"(addr), "r"(rank));
    return r;
}
__device__ __forceinline__ void mbar_init(uint32_t mbar, uint32_t cnt) {
    asm volatile("mbarrier.init.shared.b64 [%0], %1;" :: "r"(mbar), "r"(cnt) : "memory");
}
__device__ __forceinline__ void mbar_arrive_expect_tx(uint32_t mbar, uint32_t tx) {
    asm volatile("mbarrier.arrive.expect_tx.shared.b64 _, [%0], %1;"
                 :: "r"(mbar), "r"(tx) : "memory");
}
__device__ __forceinline__ void mbar_wait_parity(uint32_t mbar, uint32_t parity) {
    asm volatile(
        "{\n\t"
        ".reg .pred P;\n\t"
        "WAIT_%=:\n\t"
        "mbarrier.try_wait.parity.acquire.cta.shared::cta.b64 P, [%0], %1, 0x989680;\n\t"
        "@P bra.uni DONE_%=;\n\t"
        "bra.uni WAIT_%=;\n\t"
        "DONE_%=:\n\t"
        "}"
        :: "r"(mbar), "r"(parity) : "memory");
}
// DSMEM bulk copy: local shared -> peer CTA shared, tx-signals peer's mbarrier.
__device__ __forceinline__ void bulk_dsmem(uint32_t dst_cluster, uint32_t src_cta,
                                           uint32_t bytes, uint32_t mbar_cluster) {
    asm volatile(
        "cp.async.bulk.shared::cluster.shared::cta.mbarrier::complete_tx::bytes "
        "[%0], [%1], %2, [%3];"
        :: "r"(dst_cluster), "r"(src_cta), "r"(bytes), "r"(mbar_cluster) : "memory");
}
__device__ __forceinline__ void fence_proxy_async_cta() {
    asm volatile("fence.proxy.async.shared::cta;" ::: "memory");
}
// Packed dual-fp32 FMA: d.lo += a.lo*b.lo ; d.hi += a.hi*b.hi
__device__ __forceinline__ void ffma2(unsigned long long& d,
                                      unsigned long long a, unsigned long long b) {
    asm("fma.rn.f32x2 %0, %1, %2, %0;" : "+l"(d) : "l"(a), "l"(b));
}
__device__ __forceinline__ unsigned long long pack_f2(float lo, float hi) {
    return (unsigned long long)__float_as_uint(lo) |
           ((unsigned long long)__float_as_uint(hi) << 32);
}
__device__ __forceinline__ float lo_f(unsigned long long v) {
    return __uint_as_float((unsigned int)v);
}
__device__ __forceinline__ float hi_f(unsigned long long v) {
    return __uint_as_float((unsigned int)(v >> 32));
}

// ---------------------------------------------------------------------------
// Input GEMM: C[M,HH] = A[M,K] @ W[HH,K]^T + b1[n] + b2[n]   (unchanged)
// ---------------------------------------------------------------------------
__global__ __launch_bounds__(256) void gemm_bias_kernel(
    const float* __restrict__ A, const float* __restrict__ W,
    const float* __restrict__ b1, const float* __restrict__ b2,
    float* __restrict__ C, int M, int K)
{
    __shared__ float As[2][16][132];
    __shared__ float Ws[2][16][132];

    const int m0  = blockIdx.x * 128;
    const int n0  = blockIdx.y * 128;
    const int tid = threadIdx.x;
    const int tx  = tid & 15;
    const int ty  = tid >> 4;

    const int v0 = tid, v1 = tid + 256;
    const int r0 = v0 >> 2, c0 = (v0 & 3) * 4;
    const int r1 = v1 >> 2, c1 = (v1 & 3) * 4;

    const float* A0 = A + (size_t)(m0 + r0) * K + c0;
    const float* A1 = A + (size_t)(m0 + r1) * K + c1;
    const float* W0 = W + (size_t)(n0 + r0) * K + c0;
    const float* W1 = W + (size_t)(n0 + r1) * K + c1;

    float4 ra0, ra1, rw0, rw1;

    ra0 = *(const float4*)A0;  ra1 = *(const float4*)A1;
    rw0 = *(const float4*)W0;  rw1 = *(const float4*)W1;
    As[0][c0 + 0][r0] = ra0.x; As[0][c0 + 1][r0] = ra0.y;
    As[0][c0 + 2][r0] = ra0.z; As[0][c0 + 3][r0] = ra0.w;
    As[0][c1 + 0][r1] = ra1.x; As[0][c1 + 1][r1] = ra1.y;
    As[0][c1 + 2][r1] = ra1.z; As[0][c1 + 3][r1] = ra1.w;
    Ws[0][c0 + 0][r0] = rw0.x; Ws[0][c0 + 1][r0] = rw0.y;
    Ws[0][c0 + 2][r0] = rw0.z; Ws[0][c0 + 3][r0] = rw0.w;
    Ws[0][c1 + 0][r1] = rw1.x; Ws[0][c1 + 1][r1] = rw1.y;
    Ws[0][c1 + 2][r1] = rw1.z; Ws[0][c1 + 3][r1] = rw1.w;
    __syncthreads();

    float acc[8][8];
#pragma unroll
    for (int i = 0; i < 8; i++)
#pragma unroll
        for (int j = 0; j < 8; j++) acc[i][j] = 0.0f;

    const int NT = K / 16;
    for (int kt = 0; kt < NT; kt++) {
        const int p = kt & 1;
        if (kt + 1 < NT) {
            const int koff = (kt + 1) * 16;
            ra0 = *(const float4*)(A0 + koff);
            ra1 = *(const float4*)(A1 + koff);
            rw0 = *(const float4*)(W0 + koff);
            rw1 = *(const float4*)(W1 + koff);
        }

#pragma unroll
        for (int k = 0; k < 16; k++) {
            float4 a0 = *(const float4*)&As[p][k][ty * 8];
            float4 a1 = *(const float4*)&As[p][k][ty * 8 + 4];
            float4 bq0 = *(const float4*)&Ws[p][k][tx * 8];
            float4 bq1 = *(const float4*)&Ws[p][k][tx * 8 + 4];
            float a[8] = {a0.x, a0.y, a0.z, a0.w, a1.x, a1.y, a1.z, a1.w};
            float b[8] = {bq0.x, bq0.y, bq0.z, bq0.w, bq1.x, bq1.y, bq1.z, bq1.w};
#pragma unroll
            for (int i = 0; i < 8; i++)
#pragma unroll
                for (int j = 0; j < 8; j++)
                    acc[i][j] = fmaf(a[i], b[j], acc[i][j]);
        }

        if (kt + 1 < NT) {
            const int q = p ^ 1;
            As[q][c0 + 0][r0] = ra0.x; As[q][c0 + 1][r0] = ra0.y;
            As[q][c0 + 2][r0] = ra0.z; As[q][c0 + 3][r0] = ra0.w;
            As[q][c1 + 0][r1] = ra1.x; As[q][c1 + 1][r1] = ra1.y;
            As[q][c1 + 2][r1] = ra1.z; As[q][c1 + 3][r1] = ra1.w;
            Ws[q][c0 + 0][r0] = rw0.x; Ws[q][c0 + 1][r0] = rw0.y;
            Ws[q][c0 + 2][r0] = rw0.z; Ws[q][c0 + 3][r0] = rw0.w;
            Ws[q][c1 + 0][r1] = rw1.x; Ws[q][c1 + 1][r1] = rw1.y;
            Ws[q][c1 + 2][r1] = rw1.z; Ws[q][c1 + 3][r1] = rw1.w;
            __syncthreads();
        }
    }

    float bias[8];
#pragma unroll
    for (int j = 0; j < 8; j++) {
        int n = n0 + tx * 8 + j;
        bias[j] = b1[n] + b2[n];
    }
#pragma unroll
    for (int i = 0; i < 8; i++) {
        float* crow = C + (size_t)(m0 + ty * 8 + i) * HH + n0 + tx * 8;
        float4 o0 = make_float4(acc[i][0] + bias[0], acc[i][1] + bias[1],
                                acc[i][2] + bias[2], acc[i][3] + bias[3]);
        float4 o1 = make_float4(acc[i][4] + bias[4], acc[i][5] + bias[5],
                                acc[i][6] + bias[6], acc[i][7] + bias[7]);
        *(float4*)(crow)     = o0;
        *(float4*)(crow + 4) = o1;
    }
}

// ---------------------------------------------------------------------------
// Persistent recurrence kernel: cluster DSMEM BULK all-gather + FFMA2 compute.
// hs layout is slice-major: hs[phase][slice s][b][64] so each CTA's step
// contribution is one contiguous 1KB block, exchanged with 8 bulk copies.
// Inner product pairs along k: acc2 u64 = (even-k partial, odd-k partial).
// ---------------------------------------------------------------------------
__global__ __launch_bounds__(256, 1) __cluster_dims__(NJ, 1, 1)
void recur_kernel(
    const float* __restrict__ Z, const float* __restrict__ Whh,
    float* __restrict__ Y)
{
    __shared__ float hs[2][NJ][BSL][HSL];        // 16 KB double-buffered h (slice-major)
    __shared__ float red[BSL][KC][HSL];          // 4 KB partial sums
    __shared__ float stage[2][BSL][HSL];         // 2 KB staging (double-buffered)
    __shared__ alignas(8) unsigned long long mbar[2];

    const int j    = blockIdx.x;                 // hidden slice = cluster rank
    const int i    = blockIdx.y;                 // batch group
    const int tid  = threadIdx.x;
    const int kc   = tid >> 6;                   // 0..3 : k-chunk of 128
    const int jloc = tid & 63;                   // 0..63
    const int b0   = i * BSL;

    const uint32_t hs_base    = smem_u32(&hs[0][0][0][0]);
    const uint32_t mbar_base  = smem_u32(&mbar[0]);
    const uint32_t stage_base = smem_u32(&stage[0][0][0]);

    if (tid == 0) {
        mbar_init(mbar_base + 0, 1);
        mbar_init(mbar_base + 8, 1);
        mbar_arrive_expect_tx(mbar_base + 0, HS_BYTES);
        mbar_arrive_expect_tx(mbar_base + 8, HS_BYTES);
    }
    asm volatile("barrier.cluster.arrive.aligned;" ::: "memory");
    asm volatile("barrier.cluster.wait.aligned;"  ::: "memory");

    // Peer addresses (only threads 0..NJ-1 use index tid)
    uint32_t my_peer_hs = 0, my_peer_mb = 0;
    if (tid < NJ) {
        my_peer_hs = mapa_u32(hs_base,   (uint32_t)tid);
        my_peer_mb = mapa_u32(mbar_base, (uint32_t)tid);
    }

    // Load my Whh chunk as 64 packed (even,odd) f32 pairs.
    // w2[p] = (Whh_row[kc*128 + 2p], Whh_row[kc*128 + 2p+1])
    unsigned long long w2[64];
    {
        const float* wrow = Whh + (size_t)(j * HSL + jloc) * HH + kc * 128;
#pragma unroll
        for (int q = 0; q < 32; q++) {
            float4 v = *(const float4*)(wrow + q * 4);
            w2[q * 2 + 0] = pack_f2(v.x, v.y);
            w2[q * 2 + 1] = pack_f2(v.z, v.w);
        }
    }

    // Output mapping
    const int rb  = tid >> 6;                    // batch row 0..3
    const int rjj = tid & 63;                    // hidden idx within slice
    const int brow = b0 + rb;
    const int jg   = j * HSL + rjj;
    const size_t zy_off = (size_t)brow * HH + jg;

    int par0 = 0, par1 = 0;

    for (int t = 0; t < TT; t++) {
        const int ph = t & 1;

        // Prefetch pre-activation (overlaps wait below)
        float zv = __ldcs(Z + (size_t)t * BB * HH + zy_off);

        float acc = 0.0f;
        if (t > 0) {
            if (ph == 0) { mbar_wait_parity(mbar_base + 0, par0); par0 ^= 1; }
            else         { mbar_wait_parity(mbar_base + 8, par1); par1 ^= 1; }
            if (tid == 0)
                mbar_arrive_expect_tx(mbar_base + (ph ? 8 : 0), HS_BYTES);

            // acc2[b] = packed (even-k, odd-k) partial sums over my 128-k chunk
            // (slices 2*kc and 2*kc+1 of hs).
            unsigned long long acc2[BSL];
#pragma unroll
            for (int b = 0; b < BSL; b++) acc2[b] = pack_f2(0.0f, 0.0f);

#pragma unroll
            for (int ss = 0; ss < 2; ss++) {
                const int s = kc * 2 + ss;
#pragma unroll
                for (int b = 0; b < BSL; b++) {
                    const ulonglong2* hp =
                        (const ulonglong2*)&hs[ph][s][b][0];   // 16 x (2 packed pairs)
#pragma unroll
                    for (int q = 0; q < 16; q++) {
                        ulonglong2 hv = hp[q];
                        ffma2(acc2[b], hv.x, w2[ss * 32 + q * 2 + 0]);
                        ffma2(acc2[b], hv.y, w2[ss * 32 + q * 2 + 1]);
                    }
                }
            }
#pragma unroll
            for (int b = 0; b < BSL; b++)
                red[b][kc][jloc] = lo_f(acc2[b]) + hi_f(acc2[b]);
            __syncthreads();

#pragma unroll
            for (int c = 0; c < KC; c++) acc += red[rb][c][rjj];
        }

        // h_new = tanh(acc + z)
        float val = tanhf(acc + zv);
        Y[(size_t)t * BB * HH + zy_off] = val;

        // Stage contribution contiguously, then 8 bulk copies (1 KB each)
        // deliver it into every cluster CTA's hs[ph^1][j] with tx-signal.
        if (t + 1 < TT) {
            const int sph = t & 1;               // stage buffer parity
            stage[sph][rb][rjj] = val;
            __syncthreads();
            if (tid < NJ) {
                fence_proxy_async_cta();
                const uint32_t src = stage_base + (uint32_t)sph * SLICE_BYTES;
                const uint32_t dst = my_peer_hs
                    + (uint32_t)(ph ^ 1) * HS_BYTES + (uint32_t)j * SLICE_BYTES;
                const uint32_t mb  = my_peer_mb + (uint32_t)(ph ^ 1) * 8;
                bulk_dsmem(dst, src, SLICE_BYTES, mb);
            }
        } else {
            __syncthreads();                     // uniform red[] protection
        }
    }

    asm volatile("barrier.cluster.arrive.aligned;" ::: "memory");
    asm volatile("barrier.cluster.wait.aligned;"  ::: "memory");
}

// ---------------------------------------------------------------------------
extern "C" void kernel_launch(void* const* d_in, const int* in_sizes, int n_in,
                              void* d_out, int out_size)
{
    const float* Xt   = (const float*)d_in[0];
    const float* ihW0 = (const float*)d_in[1];
    const float* ihB0 = (const float*)d_in[2];
    const float* hhW0 = (const float*)d_in[3];
    const float* hhB0 = (const float*)d_in[4];
    const float* ihW1 = (const float*)d_in[5];
    const float* ihB1 = (const float*)d_in[6];
    const float* hhW1 = (const float*)d_in[7];
    const float* hhB1 = (const float*)d_in[8];
    float* out = (float*)d_out;

    float *zp = nullptr, *y0p = nullptr;
    cudaGetSymbolAddress((void**)&zp,  g_Z);
    cudaGetSymbolAddress((void**)&y0p, g_Y0);

    dim3 ggrid(TT * BB / 128, HH / 128);
    dim3 rgrid(NJ, NI);

    // Layer 0
    gemm_bias_kernel<<<ggrid, 256>>>(Xt, ihW0, ihB0, hhB0, zp, TT * BB, DD);
    recur_kernel<<<rgrid, 256>>>(zp, hhW0, y0p);

    // Layer 1
    gemm_bias_kernel<<<ggrid, 256>>>(y0p, ihW1, ihB1, hhB1, zp, TT * BB, HH);
    recur_kernel<<<rgrid, 256>>>(zp, hhW1, out);
}

// round 7
// speedup vs baseline: 1.9184x; 1.0600x over previous
#include <cuda_runtime.h>
#include <cuda_bf16.h>
#include <cstdint>
#include <cstddef>

#define TT 1024
#define BB 64
#define DD 512
#define HH 512

// Recurrence partition: NI batch-groups (clusters) x NJ hidden-slices
#define NI 16
#define NJ 8
#define BSL (BB / NI)        // 4 batch rows per group
#define HSL (HH / NJ)        // 64 hidden units per slice
#define KC  4                // k-chunks of 128 per CTA
#define SLICE_BYTES (BSL * HSL * 4)
#define HS_BYTES (NJ * SLICE_BYTES)

// Device scratch (no cudaMalloc allowed)
__device__ float g_Z [(size_t)TT * BB * HH];
__device__ float g_Y0[(size_t)TT * BB * HH];
__device__ __nv_bfloat16 g_Ahi[(size_t)TT * BB * DD];
__device__ __nv_bfloat16 g_Alo[(size_t)TT * BB * DD];
__device__ __nv_bfloat16 g_Whi[(size_t)HH * DD];
__device__ __nv_bfloat16 g_Wlo[(size_t)HH * DD];

// ---------------------------------------------------------------------------
// PTX helpers
// ---------------------------------------------------------------------------
__device__ __forceinline__ uint32_t smem_u32(const void* p) {
    uint32_t a;
    asm("{ .reg .u64 t; cvta.to.shared.u64 t, %1; cvt.u32.u64 %0, t; }"
        : "=r"(a) : "l"(p));
    return a;
}
__device__ __forceinline__ uint32_t mapa_u32(uint32_t addr, uint32_t rank) {
    uint32_t r;
    asm("mapa.shared::cluster.u32 %0, %1, %2;" : "=r"(r) : "r"(addr), "r"(rank));
    return r;
}
__device__ __forceinline__ void mbar_init(uint32_t mbar, uint32_t cnt) {
    asm volatile("mbarrier.init.shared.b64 [%0], %1;" :: "r"(mbar), "r"(cnt) : "memory");
}
__device__ __forceinline__ void mbar_arrive_expect_tx(uint32_t mbar, uint32_t tx) {
    asm volatile("mbarrier.arrive.expect_tx.shared.b64 _, [%0], %1;"
                 :: "r"(mbar), "r"(tx) : "memory");
}
__device__ __forceinline__ void mbar_wait_parity(uint32_t mbar, uint32_t parity) {
    asm volatile(
        "{\n\t"
        ".reg .pred P;\n\t"
        "WAIT_%=:\n\t"
        "mbarrier.try_wait.parity.acquire.cta.shared::cta.b64 P, [%0], %1, 0x989680;\n\t"
        "@P bra.uni DONE_%=;\n\t"
        "bra.uni WAIT_%=;\n\t"
        "DONE_%=:\n\t"
        "}"
        :: "r"(mbar), "r"(parity) : "memory");
}
__device__ __forceinline__ void bulk_dsmem(uint32_t dst_cluster, uint32_t src_cta,
                                           uint32_t bytes, uint32_t mbar_cluster) {
    asm volatile(
        "cp.async.bulk.shared::cluster.shared::cta.mbarrier::complete_tx::bytes "
        "[%0], [%1], %2, [%3];"
        :: "r"(dst_cluster), "r"(src_cta), "r"(bytes), "r"(mbar_cluster) : "memory");
}
__device__ __forceinline__ void fence_proxy_async_cta() {
    asm volatile("fence.proxy.async.shared::cta;" ::: "memory");
}
__device__ __forceinline__ void ffma2(unsigned long long& d,
                                      unsigned long long a, unsigned long long b) {
    asm("fma.rn.f32x2 %0, %1, %2, %0;" : "+l"(d) : "l"(a), "l"(b));
}
__device__ __forceinline__ unsigned long long pack_f2(float lo, float hi) {
    return (unsigned long long)__float_as_uint(lo) |
           ((unsigned long long)__float_as_uint(hi) << 32);
}
__device__ __forceinline__ float lo_f(unsigned long long v) {
    return __uint_as_float((unsigned int)v);
}
__device__ __forceinline__ float hi_f(unsigned long long v) {
    return __uint_as_float((unsigned int)(v >> 32));
}

// mma.sync m16n8k16 bf16 (sm_80+ baseline PTX: safe at compute_103)
__device__ __forceinline__ void mma16816(float* d, const uint32_t* a, const uint32_t* b) {
    asm volatile(
        "mma.sync.aligned.m16n8k16.row.col.f32.bf16.bf16.f32 "
        "{%0,%1,%2,%3}, {%4,%5,%6,%7}, {%8,%9}, {%0,%1,%2,%3};"
        : "+f"(d[0]), "+f"(d[1]), "+f"(d[2]), "+f"(d[3])
        : "r"(a[0]), "r"(a[1]), "r"(a[2]), "r"(a[3]), "r"(b[0]), "r"(b[1]));
}
__device__ __forceinline__ void ldsm_x4(uint32_t* r, uint32_t addr) {
    asm volatile("ldmatrix.sync.aligned.m8n8.x4.shared.b16 {%0,%1,%2,%3}, [%4];"
        : "=r"(r[0]), "=r"(r[1]), "=r"(r[2]), "=r"(r[3]) : "r"(addr));
}

// ---------------------------------------------------------------------------
// Split-bf16 conversion: x -> (hi, lo) with hi = bf16(x), lo = bf16(x - hi)
// ---------------------------------------------------------------------------
__global__ void split_kernel(const float* __restrict__ src,
                             __nv_bfloat16* __restrict__ hi,
                             __nv_bfloat16* __restrict__ lo, int n)
{
    int idx = blockIdx.x * blockDim.x + threadIdx.x;
    int stride = gridDim.x * blockDim.x;
    for (int i = idx; i < n; i += stride) {
        float x = src[i];
        __nv_bfloat16 h = __float2bfloat16(x);
        hi[i] = h;
        lo[i] = __float2bfloat16(x - __bfloat162float(h));
    }
}

// ---------------------------------------------------------------------------
// HMMA GEMM: C[M,512] = (Ahi+Alo)[M,512] @ (Whi+Wlo)[512,512]^T + b1 + b2
// 3-product split-bf16 on mma.sync.m16n8k16 (fp32 acc).
// CTA tile 128x128, 8 warps (2x4), warp tile 64x32; K-blocks of 32.
// SMEM rows padded 32->40 bf16 (80B stride): conflict-free ldmatrix.
// ---------------------------------------------------------------------------
#define KB 32
#define PAD 40

__global__ __launch_bounds__(256) void mma_gemm_kernel(
    const __nv_bfloat16* __restrict__ Ahi, const __nv_bfloat16* __restrict__ Alo,
    const __nv_bfloat16* __restrict__ Whi, const __nv_bfloat16* __restrict__ Wlo,
    const float* __restrict__ b1, const float* __restrict__ b2,
    float* __restrict__ C)
{
    __shared__ __nv_bfloat16 sAh[128][PAD];
    __shared__ __nv_bfloat16 sAl[128][PAD];
    __shared__ __nv_bfloat16 sWh[128][PAD];
    __shared__ __nv_bfloat16 sWl[128][PAD];

    const int tid   = threadIdx.x;
    const int wid   = tid >> 5;
    const int lane  = tid & 31;
    const int m0    = blockIdx.x * 128;
    const int n0    = blockIdx.y * 128;
    const int wm    = (wid >> 2) * 64;      // warp m offset (0 / 64)
    const int wn    = (wid & 3) * 32;       // warp n offset

    float acc[4][4][4];                     // [mf][nf][reg]
#pragma unroll
    for (int i = 0; i < 4; i++)
#pragma unroll
        for (int j = 0; j < 4; j++)
#pragma unroll
            for (int r = 0; r < 4; r++) acc[i][j][r] = 0.0f;

    // ldmatrix source addresses (per-thread, advance col by ks*16 later)
    // A-frag: row = wm + mf*16 + lane%16, col = (lane/16)*8
    const int ar = lane & 15, ac = (lane >> 4) * 8;
    // B-frag pair: n = wn + np*16 + (lane&7) + ((lane>>4)<<3), k = ((lane>>3)&1)*8
    const int br = (lane & 7) + ((lane >> 4) << 3), bc = ((lane >> 3) & 1) * 8;

    for (int kb = 0; kb < DD / KB; kb++) {
        const int k0 = kb * KB;
        // Load 4 tiles: 128 rows x 32 bf16 each; 4 chunks(16B)/row; 2 chunks/thread/tile.
#pragma unroll
        for (int tile = 0; tile < 4; tile++) {
            const __nv_bfloat16* src;
            __nv_bfloat16 (*dst)[PAD];
            int rowbase;
            if      (tile == 0) { src = Ahi; dst = sAh; rowbase = m0; }
            else if (tile == 1) { src = Alo; dst = sAl; rowbase = m0; }
            else if (tile == 2) { src = Whi; dst = sWh; rowbase = n0; }
            else                { src = Wlo; dst = sWl; rowbase = n0; }
#pragma unroll
            for (int it = 0; it < 2; it++) {
                int idx = it * 256 + tid;        // 0..511
                int r   = idx >> 2;              // 0..127
                int c   = (idx & 3) * 8;         // bf16 col 0,8,16,24
                uint4 v = *(const uint4*)(src + (size_t)(rowbase + r) * DD + k0 + c);
                *(uint4*)&dst[r][c] = v;
            }
        }
        __syncthreads();

#pragma unroll
        for (int ks = 0; ks < 2; ks++) {
            const int kk = ks * 16;
            uint32_t fAh[4][4], fAl[4][4], fWh[2][4], fWl[2][4];
#pragma unroll
            for (int mf = 0; mf < 4; mf++) {
                ldsm_x4(fAh[mf], smem_u32(&sAh[wm + mf * 16 + ar][kk + ac]));
                ldsm_x4(fAl[mf], smem_u32(&sAl[wm + mf * 16 + ar][kk + ac]));
            }
#pragma unroll
            for (int np = 0; np < 2; np++) {
                ldsm_x4(fWh[np], smem_u32(&sWh[wn + np * 16 + br][kk + bc]));
                ldsm_x4(fWl[np], smem_u32(&sWl[wn + np * 16 + br][kk + bc]));
            }
            // 3 products: Ah*Wh + Ah*Wl + Al*Wh
#pragma unroll
            for (int mf = 0; mf < 4; mf++) {
#pragma unroll
                for (int np = 0; np < 2; np++) {
#pragma unroll
                    for (int h = 0; h < 2; h++) {    // n-frag within pair
                        const int nf = np * 2 + h;
                        mma16816(acc[mf][nf], fAh[mf], &fWh[np][h * 2]);
                        mma16816(acc[mf][nf], fAh[mf], &fWl[np][h * 2]);
                        mma16816(acc[mf][nf], fAl[mf], &fWh[np][h * 2]);
                    }
                }
            }
        }
        __syncthreads();
    }

    // Epilogue: d0,d1 -> row lane/4, cols 2*(lane%4)+{0,1}; d2,d3 -> row+8.
    const int erow = lane >> 2;
    const int ecol = (lane & 3) * 2;
#pragma unroll
    for (int mf = 0; mf < 4; mf++) {
#pragma unroll
        for (int nf = 0; nf < 4; nf++) {
            const int n = n0 + wn + nf * 8 + ecol;
            const float bv0 = __ldg(b1 + n)     + __ldg(b2 + n);
            const float bv1 = __ldg(b1 + n + 1) + __ldg(b2 + n + 1);
            const int r0 = m0 + wm + mf * 16 + erow;
            float2 o0 = make_float2(acc[mf][nf][0] + bv0, acc[mf][nf][1] + bv1);
            float2 o1 = make_float2(acc[mf][nf][2] + bv0, acc[mf][nf][3] + bv1);
            *(float2*)(C + (size_t)r0 * HH + n)       = o0;
            *(float2*)(C + (size_t)(r0 + 8) * HH + n) = o1;
        }
    }
}

// ---------------------------------------------------------------------------
// Persistent recurrence kernel (unchanged from R5 passing version):
// cluster DSMEM BULK all-gather + FFMA2 compute.
// ---------------------------------------------------------------------------
__global__ __launch_bounds__(256, 1) __cluster_dims__(NJ, 1, 1)
void recur_kernel(
    const float* __restrict__ Z, const float* __restrict__ Whh,
    float* __restrict__ Y)
{
    __shared__ float hs[2][NJ][BSL][HSL];
    __shared__ float red[BSL][KC][HSL];
    __shared__ float stage[2][BSL][HSL];
    __shared__ alignas(8) unsigned long long mbar[2];

    const int j    = blockIdx.x;
    const int i    = blockIdx.y;
    const int tid  = threadIdx.x;
    const int kc   = tid >> 6;
    const int jloc = tid & 63;
    const int b0   = i * BSL;

    const uint32_t hs_base    = smem_u32(&hs[0][0][0][0]);
    const uint32_t mbar_base  = smem_u32(&mbar[0]);
    const uint32_t stage_base = smem_u32(&stage[0][0][0]);

    if (tid == 0) {
        mbar_init(mbar_base + 0, 1);
        mbar_init(mbar_base + 8, 1);
        mbar_arrive_expect_tx(mbar_base + 0, HS_BYTES);
        mbar_arrive_expect_tx(mbar_base + 8, HS_BYTES);
    }
    asm volatile("barrier.cluster.arrive.aligned;" ::: "memory");
    asm volatile("barrier.cluster.wait.aligned;"  ::: "memory");

    uint32_t my_peer_hs = 0, my_peer_mb = 0;
    if (tid < NJ) {
        my_peer_hs = mapa_u32(hs_base,   (uint32_t)tid);
        my_peer_mb = mapa_u32(mbar_base, (uint32_t)tid);
    }

    unsigned long long w2[64];
    {
        const float* wrow = Whh + (size_t)(j * HSL + jloc) * HH + kc * 128;
#pragma unroll
        for (int q = 0; q < 32; q++) {
            float4 v = *(const float4*)(wrow + q * 4);
            w2[q * 2 + 0] = pack_f2(v.x, v.y);
            w2[q * 2 + 1] = pack_f2(v.z, v.w);
        }
    }

    const int rb  = tid >> 6;
    const int rjj = tid & 63;
    const int brow = b0 + rb;
    const int jg   = j * HSL + rjj;
    const size_t zy_off = (size_t)brow * HH + jg;

    int par0 = 0, par1 = 0;

    for (int t = 0; t < TT; t++) {
        const int ph = t & 1;

        float zv = __ldcs(Z + (size_t)t * BB * HH + zy_off);

        float acc = 0.0f;
        if (t > 0) {
            if (ph == 0) { mbar_wait_parity(mbar_base + 0, par0); par0 ^= 1; }
            else         { mbar_wait_parity(mbar_base + 8, par1); par1 ^= 1; }
            if (tid == 0)
                mbar_arrive_expect_tx(mbar_base + (ph ? 8 : 0), HS_BYTES);

            unsigned long long acc2[BSL];
#pragma unroll
            for (int b = 0; b < BSL; b++) acc2[b] = pack_f2(0.0f, 0.0f);

#pragma unroll
            for (int ss = 0; ss < 2; ss++) {
                const int s = kc * 2 + ss;
#pragma unroll
                for (int b = 0; b < BSL; b++) {
                    const ulonglong2* hp = (const ulonglong2*)&hs[ph][s][b][0];
#pragma unroll
                    for (int q = 0; q < 16; q++) {
                        ulonglong2 hv = hp[q];
                        ffma2(acc2[b], hv.x, w2[ss * 32 + q * 2 + 0]);
                        ffma2(acc2[b], hv.y, w2[ss * 32 + q * 2 + 1]);
                    }
                }
            }
#pragma unroll
            for (int b = 0; b < BSL; b++)
                red[b][kc][jloc] = lo_f(acc2[b]) + hi_f(acc2[b]);
            __syncthreads();

#pragma unroll
            for (int c = 0; c < KC; c++) acc += red[rb][c][rjj];
        }

        float val = tanhf(acc + zv);
        Y[(size_t)t * BB * HH + zy_off] = val;

        if (t + 1 < TT) {
            const int sph = t & 1;
            stage[sph][rb][rjj] = val;
            __syncthreads();
            if (tid < NJ) {
                fence_proxy_async_cta();
                const uint32_t src = stage_base + (uint32_t)sph * SLICE_BYTES;
                const uint32_t dst = my_peer_hs
                    + (uint32_t)(ph ^ 1) * HS_BYTES + (uint32_t)j * SLICE_BYTES;
                const uint32_t mb  = my_peer_mb + (uint32_t)(ph ^ 1) * 8;
                bulk_dsmem(dst, src, SLICE_BYTES, mb);
            }
        } else {
            __syncthreads();
        }
    }

    asm volatile("barrier.cluster.arrive.aligned;" ::: "memory");
    asm volatile("barrier.cluster.wait.aligned;"  ::: "memory");
}

// ---------------------------------------------------------------------------
extern "C" void kernel_launch(void* const* d_in, const int* in_sizes, int n_in,
                              void* d_out, int out_size)
{
    const float* Xt   = (const float*)d_in[0];
    const float* ihW0 = (const float*)d_in[1];
    const float* ihB0 = (const float*)d_in[2];
    const float* hhW0 = (const float*)d_in[3];
    const float* hhB0 = (const float*)d_in[4];
    const float* ihW1 = (const float*)d_in[5];
    const float* ihB1 = (const float*)d_in[6];
    const float* hhW1 = (const float*)d_in[7];
    const float* hhB1 = (const float*)d_in[8];
    float* out = (float*)d_out;

    float *zp = nullptr, *y0p = nullptr;
    __nv_bfloat16 *ahi, *alo, *whi, *wlo;
    cudaGetSymbolAddress((void**)&zp,  g_Z);
    cudaGetSymbolAddress((void**)&y0p, g_Y0);
    cudaGetSymbolAddress((void**)&ahi, g_Ahi);
    cudaGetSymbolAddress((void**)&alo, g_Alo);
    cudaGetSymbolAddress((void**)&whi, g_Whi);
    cudaGetSymbolAddress((void**)&wlo, g_Wlo);

    dim3 ggrid(TT * BB / 128, HH / 128);   // (512, 4)
    dim3 rgrid(NJ, NI);

    const int NX = TT * BB * DD;
    const int NW = HH * DD;

    // ---- Layer 0 ----
    split_kernel<<<2048, 256>>>(Xt,   ahi, alo, NX);
    split_kernel<<<512, 256>>>(ihW0, whi, wlo, NW);
    mma_gemm_kernel<<<ggrid, 256>>>(ahi, alo, whi, wlo, ihB0, hhB0, zp);
    recur_kernel<<<rgrid, 256>>>(zp, hhW0, y0p);

    // ---- Layer 1 ----
    split_kernel<<<2048, 256>>>(y0p,  ahi, alo, NX);
    split_kernel<<<512, 256>>>(ihW1, whi, wlo, NW);
    mma_gemm_kernel<<<ggrid, 256>>>(ahi, alo, whi, wlo, ihB1, hhB1, zp);
    recur_kernel<<<rgrid, 256>>>(zp, hhW1, out);
}

// round 8
// speedup vs baseline: 2.0139x; 1.0498x over previous
#include <cuda_runtime.h>
#include <cuda_bf16.h>
#include <cstdint>
#include <cstddef>

#define TT 1024
#define BB 64
#define DD 512
#define HH 512

// Recurrence partition: NI batch-groups (clusters) x NJ hidden-slices
#define NI 16
#define NJ 8
#define BSL (BB / NI)        // 4 batch rows per group
#define HSL (HH / NJ)        // 64 hidden units per slice
#define KC  4                // k-chunks of 128 per CTA
#define SLICE_BYTES (BSL * HSL * 4)
#define HS_BYTES (NJ * SLICE_BYTES)

// Device scratch (no cudaMalloc allowed)
__device__ float g_Z [(size_t)TT * BB * HH];
__device__ float g_Y0[(size_t)TT * BB * HH];
__device__ __nv_bfloat16 g_Ahi[(size_t)TT * BB * DD];
__device__ __nv_bfloat16 g_Alo[(size_t)TT * BB * DD];
__device__ __nv_bfloat16 g_Whi[(size_t)HH * DD];
__device__ __nv_bfloat16 g_Wlo[(size_t)HH * DD];

// ---------------------------------------------------------------------------
// PTX helpers
// ---------------------------------------------------------------------------
__device__ __forceinline__ uint32_t smem_u32(const void* p) {
    uint32_t a;
    asm("{ .reg .u64 t; cvta.to.shared.u64 t, %1; cvt.u32.u64 %0, t; }"
        : "=r"(a) : "l"(p));
    return a;
}
__device__ __forceinline__ uint32_t mapa_u32(uint32_t addr, uint32_t rank) {
    uint32_t r;
    asm("mapa.shared::cluster.u32 %0, %1, %2;" : "=r"(r) : "r"(addr), "r"(rank));
    return r;
}
__device__ __forceinline__ void mbar_init(uint32_t mbar, uint32_t cnt) {
    asm volatile("mbarrier.init.shared.b64 [%0], %1;" :: "r"(mbar), "r"(cnt) : "memory");
}
__device__ __forceinline__ void mbar_arrive_expect_tx(uint32_t mbar, uint32_t tx) {
    asm volatile("mbarrier.arrive.expect_tx.shared.b64 _, [%0], %1;"
                 :: "r"(mbar), "r"(tx) : "memory");
}
__device__ __forceinline__ void mbar_wait_parity(uint32_t mbar, uint32_t parity) {
    asm volatile(
        "{\n\t"
        ".reg .pred P;\n\t"
        "WAIT_%=:\n\t"
        "mbarrier.try_wait.parity.acquire.cta.shared::cta.b64 P, [%0], %1, 0x989680;\n\t"
        "@P bra.uni DONE_%=;\n\t"
        "bra.uni WAIT_%=;\n\t"
        "DONE_%=:\n\t"
        "}"
        :: "r"(mbar), "r"(parity) : "memory");
}
__device__ __forceinline__ void bulk_dsmem(uint32_t dst_cluster, uint32_t src_cta,
                                           uint32_t bytes, uint32_t mbar_cluster) {
    asm volatile(
        "cp.async.bulk.shared::cluster.shared::cta.mbarrier::complete_tx::bytes "
        "[%0], [%1], %2, [%3];"
        :: "r"(dst_cluster), "r"(src_cta), "r"(bytes), "r"(mbar_cluster) : "memory");
}
__device__ __forceinline__ void fence_proxy_async_cta() {
    asm volatile("fence.proxy.async.shared::cta;" ::: "memory");
}
__device__ __forceinline__ void ffma2(unsigned long long& d,
                                      unsigned long long a, unsigned long long b) {
    asm("fma.rn.f32x2 %0, %1, %2, %0;" : "+l"(d) : "l"(a), "l"(b));
}
__device__ __forceinline__ unsigned long long pack_f2(float lo, float hi) {
    return (unsigned long long)__float_as_uint(lo) |
           ((unsigned long long)__float_as_uint(hi) << 32);
}
__device__ __forceinline__ float lo_f(unsigned long long v) {
    return __uint_as_float((unsigned int)v);
}
__device__ __forceinline__ float hi_f(unsigned long long v) {
    return __uint_as_float((unsigned int)(v >> 32));
}

// mma.sync m16n8k16 bf16 (sm_80+ baseline PTX: safe at compute_103)
__device__ __forceinline__ void mma16816(float* d, const uint32_t* a, const uint32_t* b) {
    asm volatile(
        "mma.sync.aligned.m16n8k16.row.col.f32.bf16.bf16.f32 "
        "{%0,%1,%2,%3}, {%4,%5,%6,%7}, {%8,%9}, {%0,%1,%2,%3};"
        : "+f"(d[0]), "+f"(d[1]), "+f"(d[2]), "+f"(d[3])
        : "r"(a[0]), "r"(a[1]), "r"(a[2]), "r"(a[3]), "r"(b[0]), "r"(b[1]));
}
__device__ __forceinline__ void ldsm_x4(uint32_t* r, uint32_t addr) {
    asm volatile("ldmatrix.sync.aligned.m8n8.x4.shared.b16 {%0,%1,%2,%3}, [%4];"
        : "=r"(r[0]), "=r"(r[1]), "=r"(r[2]), "=r"(r[3]) : "r"(addr));
}

// ---------------------------------------------------------------------------
// Split-bf16 conversion: x -> (hi, lo) with hi = bf16(x), lo = bf16(x - hi)
// ---------------------------------------------------------------------------
__global__ void split_kernel(const float* __restrict__ src,
                             __nv_bfloat16* __restrict__ hi,
                             __nv_bfloat16* __restrict__ lo, int n)
{
    int idx = blockIdx.x * blockDim.x + threadIdx.x;
    int stride = gridDim.x * blockDim.x;
    for (int i = idx; i < n; i += stride) {
        float x = src[i];
        __nv_bfloat16 h = __float2bfloat16(x);
        hi[i] = h;
        lo[i] = __float2bfloat16(x - __bfloat162float(h));
    }
}

// ---------------------------------------------------------------------------
// HMMA GEMM (unchanged from R6 passing version)
// ---------------------------------------------------------------------------
#define KB 32
#define PAD 40

__global__ __launch_bounds__(256) void mma_gemm_kernel(
    const __nv_bfloat16* __restrict__ Ahi, const __nv_bfloat16* __restrict__ Alo,
    const __nv_bfloat16* __restrict__ Whi, const __nv_bfloat16* __restrict__ Wlo,
    const float* __restrict__ b1, const float* __restrict__ b2,
    float* __restrict__ C)
{
    __shared__ __nv_bfloat16 sAh[128][PAD];
    __shared__ __nv_bfloat16 sAl[128][PAD];
    __shared__ __nv_bfloat16 sWh[128][PAD];
    __shared__ __nv_bfloat16 sWl[128][PAD];

    const int tid   = threadIdx.x;
    const int wid   = tid >> 5;
    const int lane  = tid & 31;
    const int m0    = blockIdx.x * 128;
    const int n0    = blockIdx.y * 128;
    const int wm    = (wid >> 2) * 64;
    const int wn    = (wid & 3) * 32;

    float acc[4][4][4];
#pragma unroll
    for (int i = 0; i < 4; i++)
#pragma unroll
        for (int j = 0; j < 4; j++)
#pragma unroll
            for (int r = 0; r < 4; r++) acc[i][j][r] = 0.0f;

    const int ar = lane & 15, ac = (lane >> 4) * 8;
    const int br = (lane & 7) + ((lane >> 4) << 3), bc = ((lane >> 3) & 1) * 8;

    for (int kb = 0; kb < DD / KB; kb++) {
        const int k0 = kb * KB;
#pragma unroll
        for (int tile = 0; tile < 4; tile++) {
            const __nv_bfloat16* src;
            __nv_bfloat16 (*dst)[PAD];
            int rowbase;
            if      (tile == 0) { src = Ahi; dst = sAh; rowbase = m0; }
            else if (tile == 1) { src = Alo; dst = sAl; rowbase = m0; }
            else if (tile == 2) { src = Whi; dst = sWh; rowbase = n0; }
            else                { src = Wlo; dst = sWl; rowbase = n0; }
#pragma unroll
            for (int it = 0; it < 2; it++) {
                int idx = it * 256 + tid;
                int r   = idx >> 2;
                int c   = (idx & 3) * 8;
                uint4 v = *(const uint4*)(src + (size_t)(rowbase + r) * DD + k0 + c);
                *(uint4*)&dst[r][c] = v;
            }
        }
        __syncthreads();

#pragma unroll
        for (int ks = 0; ks < 2; ks++) {
            const int kk = ks * 16;
            uint32_t fAh[4][4], fAl[4][4], fWh[2][4], fWl[2][4];
#pragma unroll
            for (int mf = 0; mf < 4; mf++) {
                ldsm_x4(fAh[mf], smem_u32(&sAh[wm + mf * 16 + ar][kk + ac]));
                ldsm_x4(fAl[mf], smem_u32(&sAl[wm + mf * 16 + ar][kk + ac]));
            }
#pragma unroll
            for (int np = 0; np < 2; np++) {
                ldsm_x4(fWh[np], smem_u32(&sWh[wn + np * 16 + br][kk + bc]));
                ldsm_x4(fWl[np], smem_u32(&sWl[wn + np * 16 + br][kk + bc]));
            }
#pragma unroll
            for (int mf = 0; mf < 4; mf++) {
#pragma unroll
                for (int np = 0; np < 2; np++) {
#pragma unroll
                    for (int h = 0; h < 2; h++) {
                        const int nf = np * 2 + h;
                        mma16816(acc[mf][nf], fAh[mf], &fWh[np][h * 2]);
                        mma16816(acc[mf][nf], fAh[mf], &fWl[np][h * 2]);
                        mma16816(acc[mf][nf], fAl[mf], &fWh[np][h * 2]);
                    }
                }
            }
        }
        __syncthreads();
    }

    const int erow = lane >> 2;
    const int ecol = (lane & 3) * 2;
#pragma unroll
    for (int mf = 0; mf < 4; mf++) {
#pragma unroll
        for (int nf = 0; nf < 4; nf++) {
            const int n = n0 + wn + nf * 8 + ecol;
            const float bv0 = __ldg(b1 + n)     + __ldg(b2 + n);
            const float bv1 = __ldg(b1 + n + 1) + __ldg(b2 + n + 1);
            const int r0 = m0 + wm + mf * 16 + erow;
            float2 o0 = make_float2(acc[mf][nf][0] + bv0, acc[mf][nf][1] + bv1);
            float2 o1 = make_float2(acc[mf][nf][2] + bv0, acc[mf][nf][3] + bv1);
            *(float2*)(C + (size_t)r0 * HH + n)       = o0;
            *(float2*)(C + (size_t)(r0 + 8) * HH + n) = o1;
        }
    }
}

// ---------------------------------------------------------------------------
// Persistent recurrence kernel v2: PER-SLICE mbarriers so each warp-pair
// starts computing as soon as ITS two h slices (2kc, 2kc+1) arrive, instead
// of waiting for all 8. Exchange latency overlaps compute; the CTA-wide
// join is the red[] reduce barrier.
// ---------------------------------------------------------------------------
__global__ __launch_bounds__(256, 1) __cluster_dims__(NJ, 1, 1)
void recur_kernel(
    const float* __restrict__ Z, const float* __restrict__ Whh,
    float* __restrict__ Y)
{
    __shared__ float hs[2][NJ][BSL][HSL];        // 16 KB double-buffered h
    __shared__ float red[BSL][KC][HSL];          // 4 KB partial sums
    __shared__ float stage[2][BSL][HSL];         // 2 KB staging
    __shared__ alignas(8) unsigned long long mbar[2][NJ];   // per-phase, per-slice

    const int j    = blockIdx.x;                 // hidden slice = cluster rank
    const int i    = blockIdx.y;                 // batch group
    const int tid  = threadIdx.x;
    const int kc   = tid >> 6;                   // warp-pair 0..3
    const int jloc = tid & 63;
    const int b0   = i * BSL;

    const uint32_t hs_base    = smem_u32(&hs[0][0][0][0]);
    const uint32_t mbar_base  = smem_u32(&mbar[0][0]);
    const uint32_t stage_base = smem_u32(&stage[0][0][0]);

    if (tid == 0) {
#pragma unroll
        for (int ph = 0; ph < 2; ph++)
#pragma unroll
            for (int s = 0; s < NJ; s++) {
                const uint32_t mb = mbar_base + (uint32_t)(ph * NJ + s) * 8;
                mbar_init(mb, 1);
                mbar_arrive_expect_tx(mb, SLICE_BYTES);
            }
    }
    asm volatile("barrier.cluster.arrive.aligned;" ::: "memory");
    asm volatile("barrier.cluster.wait.aligned;"  ::: "memory");

    uint32_t my_peer_hs = 0, my_peer_mb = 0;
    if (tid < NJ) {
        my_peer_hs = mapa_u32(hs_base,   (uint32_t)tid);
        my_peer_mb = mapa_u32(mbar_base, (uint32_t)tid);
    }

    // Whh chunk in registers as packed pairs
    unsigned long long w2[64];
    {
        const float* wrow = Whh + (size_t)(j * HSL + jloc) * HH + kc * 128;
#pragma unroll
        for (int q = 0; q < 32; q++) {
            float4 v = *(const float4*)(wrow + q * 4);
            w2[q * 2 + 0] = pack_f2(v.x, v.y);
            w2[q * 2 + 1] = pack_f2(v.z, v.w);
        }
    }

    const int rb  = tid >> 6;
    const int rjj = tid & 63;
    const int brow = b0 + rb;
    const int jg   = j * HSL + rjj;
    const size_t zy_off = (size_t)brow * HH + jg;

    // My two slice barriers (per phase)
    const uint32_t mbA0 = mbar_base + (uint32_t)(0 * NJ + 2 * kc) * 8;
    const uint32_t mbA1 = mbar_base + (uint32_t)(1 * NJ + 2 * kc) * 8;

    int par[2] = {0, 0};

    for (int t = 0; t < TT; t++) {
        const int ph = t & 1;

        float zv = __ldcs(Z + (size_t)t * BB * HH + zy_off);

        float acc = 0.0f;
        if (t > 0) {
            const uint32_t mbA = (ph == 0) ? mbA0 : mbA1;   // slice 2kc
            const uint32_t mbB = mbA + 8;                    // slice 2kc+1
            const int p = par[ph];

            unsigned long long acc2[BSL];
#pragma unroll
            for (int b = 0; b < BSL; b++) acc2[b] = pack_f2(0.0f, 0.0f);

            // ---- slice 2kc ----
            mbar_wait_parity(mbA, p);
            {
                const int s = kc * 2;
#pragma unroll
                for (int b = 0; b < BSL; b++) {
                    const ulonglong2* hp = (const ulonglong2*)&hs[ph][s][b][0];
#pragma unroll
                    for (int q = 0; q < 16; q++) {
                        ulonglong2 hv = hp[q];
                        ffma2(acc2[b], hv.x, w2[q * 2 + 0]);
                        ffma2(acc2[b], hv.y, w2[q * 2 + 1]);
                    }
                }
            }
            // ---- slice 2kc+1 ----
            mbar_wait_parity(mbB, p);
            if (jloc == 0) {        // one thread per warp-pair re-arms both
                mbar_arrive_expect_tx(mbA, SLICE_BYTES);
                mbar_arrive_expect_tx(mbB, SLICE_BYTES);
            }
            {
                const int s = kc * 2 + 1;
#pragma unroll
                for (int b = 0; b < BSL; b++) {
                    const ulonglong2* hp = (const ulonglong2*)&hs[ph][s][b][0];
#pragma unroll
                    for (int q = 0; q < 16; q++) {
                        ulonglong2 hv = hp[q];
                        ffma2(acc2[b], hv.x, w2[32 + q * 2 + 0]);
                        ffma2(acc2[b], hv.y, w2[32 + q * 2 + 1]);
                    }
                }
            }
            par[ph] = p ^ 1;

#pragma unroll
            for (int b = 0; b < BSL; b++)
                red[b][kc][jloc] = lo_f(acc2[b]) + hi_f(acc2[b]);
            __syncthreads();

#pragma unroll
            for (int c = 0; c < KC; c++) acc += red[rb][c][rjj];
        }

        float val = tanhf(acc + zv);
        Y[(size_t)t * BB * HH + zy_off] = val;

        if (t + 1 < TT) {
            const int sph = t & 1;
            stage[sph][rb][rjj] = val;
            __syncthreads();
            if (tid < NJ) {
                fence_proxy_async_cta();
                const uint32_t src = stage_base + (uint32_t)sph * SLICE_BYTES;
                const uint32_t dst = my_peer_hs
                    + (uint32_t)(ph ^ 1) * HS_BYTES + (uint32_t)j * SLICE_BYTES;
                const uint32_t mb  = my_peer_mb + (uint32_t)((ph ^ 1) * NJ + j) * 8;
                bulk_dsmem(dst, src, SLICE_BYTES, mb);
            }
        } else {
            __syncthreads();
        }
    }

    asm volatile("barrier.cluster.arrive.aligned;" ::: "memory");
    asm volatile("barrier.cluster.wait.aligned;"  ::: "memory");
}

// ---------------------------------------------------------------------------
extern "C" void kernel_launch(void* const* d_in, const int* in_sizes, int n_in,
                              void* d_out, int out_size)
{
    const float* Xt   = (const float*)d_in[0];
    const float* ihW0 = (const float*)d_in[1];
    const float* ihB0 = (const float*)d_in[2];
    const float* hhW0 = (const float*)d_in[3];
    const float* hhB0 = (const float*)d_in[4];
    const float* ihW1 = (const float*)d_in[5];
    const float* ihB1 = (const float*)d_in[6];
    const float* hhW1 = (const float*)d_in[7];
    const float* hhB1 = (const float*)d_in[8];
    float* out = (float*)d_out;

    float *zp = nullptr, *y0p = nullptr;
    __nv_bfloat16 *ahi, *alo, *whi, *wlo;
    cudaGetSymbolAddress((void**)&zp,  g_Z);
    cudaGetSymbolAddress((void**)&y0p, g_Y0);
    cudaGetSymbolAddress((void**)&ahi, g_Ahi);
    cudaGetSymbolAddress((void**)&alo, g_Alo);
    cudaGetSymbolAddress((void**)&whi, g_Whi);
    cudaGetSymbolAddress((void**)&wlo, g_Wlo);

    dim3 ggrid(TT * BB / 128, HH / 128);   // (512, 4)
    dim3 rgrid(NJ, NI);

    const int NX = TT * BB * DD;
    const int NW = HH * DD;

    // ---- Layer 0 ----
    split_kernel<<<2048, 256>>>(Xt,   ahi, alo, NX);
    split_kernel<<<512, 256>>>(ihW0, whi, wlo, NW);
    mma_gemm_kernel<<<ggrid, 256>>>(ahi, alo, whi, wlo, ihB0, hhB0, zp);
    recur_kernel<<<rgrid, 256>>>(zp, hhW0, y0p);

    // ---- Layer 1 ----
    split_kernel<<<2048, 256>>>(y0p,  ahi, alo, NX);
    split_kernel<<<512, 256>>>(ihW1, whi, wlo, NW);
    mma_gemm_kernel<<<ggrid, 256>>>(ahi, alo, whi, wlo, ihB1, hhB1, zp);
    recur_kernel<<<rgrid, 256>>>(zp, hhW1, out);
}